// round 4
// baseline (speedup 1.0000x reference)
#include <cuda_runtime.h>
#include <cuda_bf16.h>
#include <cstdint>

#define N_ROWS 16384
#define K_CODES 4096
#define D_DIM 512

#define TILE_M 128
#define TILE_N 128
#define NTILES 32                 // K_CODES / TILE_N
#define CHUNKS_PER_TILE 16        // 512 bf16 / 32 per chunk
#define TOTAL_CHUNKS 512          // NTILES * CHUNKS_PER_TILE

#define A_ROW_BYTES 1040          // 512 bf16 = 1024 B + 16 pad (conflict-free)
#define A_ROW_WORDS 260
#define A_BYTES (TILE_M * A_ROW_BYTES)        // 133120
#define B_ROW_BYTES 80            // 32 bf16 = 64 B + 16 pad
#define B_ROW_WORDS 20
#define B_STAGE_BYTES (TILE_N * B_ROW_BYTES)  // 10240
#define B_STAGES 4
#define B_TOTAL (B_STAGES * B_STAGE_BYTES)    // 40960
#define CN_OFF (A_BYTES + B_TOTAL)            // 174080
#define DYN_BYTES (CN_OFF + K_CODES * 4)      // 190464

#define MARGIN 2.0e-3f
#define MAX_CAND 32

// -------- scratch (static device globals; no allocation) --------
__device__ unsigned g_zb[N_ROWS * D_DIM / 2];   // z in bf16x2, 16 MB
__device__ unsigned g_cbb[K_CODES * D_DIM / 2]; // codebook bf16x2, 4 MB
__device__ float    g_znorm[N_ROWS];
__device__ float    g_cnorm[K_CODES];
__device__ int      g_idx[N_ROWS];
__device__ float    g_partial[N_ROWS];
__device__ int      g_cand[N_ROWS * MAX_CAND];
__device__ unsigned g_cnt[N_ROWS];

// -------- helpers --------
__device__ __forceinline__ unsigned smem_u32(const void* p){
    unsigned a;
    asm("{ .reg .u64 t; cvta.to.shared.u64 t, %1; cvt.u32.u64 %0, t; }" : "=r"(a) : "l"(p));
    return a;
}
__device__ __forceinline__ void cp16(unsigned s, const void* g){
    asm volatile("cp.async.cg.shared.global [%0], [%1], 16;" :: "r"(s), "l"(g) : "memory");
}
__device__ __forceinline__ unsigned enc_f(float f){
    unsigned b = __float_as_uint(f);
    return (b & 0x80000000u) ? ~b : (b | 0x80000000u);
}
__device__ __forceinline__ float dec_f(unsigned e){
    return (e & 0x80000000u) ? __uint_as_float(e ^ 0x80000000u) : __uint_as_float(~e);
}
__device__ __forceinline__ void mma_bf16(float& c0, float& c1, float& c2, float& c3,
                                         unsigned a0, unsigned a1, unsigned a2, unsigned a3,
                                         unsigned b0, unsigned b1){
    asm volatile(
        "mma.sync.aligned.m16n8k16.row.col.f32.bf16.bf16.f32 "
        "{%0,%1,%2,%3}, {%4,%5,%6,%7}, {%8,%9}, {%0,%1,%2,%3};"
        : "+f"(c0), "+f"(c1), "+f"(c2), "+f"(c3)
        : "r"(a0), "r"(a1), "r"(a2), "r"(a3), "r"(b0), "r"(b1));
}
__device__ __forceinline__ unsigned pack_bf2(float x, float y){
    __nv_bfloat162 h = __float22bfloat162_rn(make_float2(x, y));
    return (unsigned)__bfloat16_as_ushort(h.x) | ((unsigned)__bfloat16_as_ushort(h.y) << 16);
}

// -------- init / conversions / norms --------
__global__ void init_cnt_kernel(){
    int i = blockIdx.x * blockDim.x + threadIdx.x;
    if (i < N_ROWS) g_cnt[i] = 0u;
}
__global__ void convz_kernel(const float* __restrict__ z){
    int i = blockIdx.x * blockDim.x + threadIdx.x;
    if (i < N_ROWS * D_DIM / 4){
        float4 v = ((const float4*)z)[i];
        ((uint2*)g_zb)[i] = make_uint2(pack_bf2(v.x, v.y), pack_bf2(v.z, v.w));
    }
}
__global__ void convc_kernel(const float* __restrict__ cb){
    int i = blockIdx.x * blockDim.x + threadIdx.x;
    if (i < K_CODES * D_DIM / 4){
        float4 v = ((const float4*)cb)[i];
        ((uint2*)g_cbb)[i] = make_uint2(pack_bf2(v.x, v.y), pack_bf2(v.z, v.w));
    }
}
__global__ void znorm_kernel(const float* __restrict__ z){
    int w = (blockIdx.x * blockDim.x + threadIdx.x) >> 5;
    int lane = threadIdx.x & 31;
    if (w >= N_ROWS) return;
    const float* r = z + (size_t)w * D_DIM;
    double acc = 0.0;
    #pragma unroll 4
    for (int j = lane; j < D_DIM; j += 32){ float v = r[j]; acc += (double)v * (double)v; }
    #pragma unroll
    for (int o = 16; o > 0; o >>= 1) acc += __shfl_down_sync(0xffffffffu, acc, o);
    if (lane == 0) g_znorm[w] = (float)acc;
}
__global__ void cnorm_kernel(const float* __restrict__ cb){
    int w = (blockIdx.x * blockDim.x + threadIdx.x) >> 5;
    int lane = threadIdx.x & 31;
    if (w >= K_CODES) return;
    const float* r = cb + (size_t)w * D_DIM;
    double acc = 0.0;
    #pragma unroll 4
    for (int j = lane; j < D_DIM; j += 32){ float v = r[j]; acc += (double)v * (double)v; }
    #pragma unroll
    for (int o = 16; o > 0; o >>= 1) acc += __shfl_down_sync(0xffffffffu, acc, o);
    if (lane == 0) g_cnorm[w] = (float)acc;
}

// -------- B chunk loader --------
__device__ __forceinline__ void load_B(unsigned smB, int ch, int tid){
    const int nt = ch >> 4, kc = ch & 15;
    const unsigned dst = smB + (unsigned)((ch & 3) * B_STAGE_BYTES);
    const char* src = (const char*)g_cbb;
    #pragma unroll
    for (int i = 0; i < 2; i++){
        int f = tid + i * 256;
        int r = f >> 2, qq = f & 3;
        cp16(dst + (unsigned)(r * B_ROW_BYTES + qq * 16),
             src + (((size_t)(nt * TILE_N + r)) << 10) + kc * 64 + qq * 16);
    }
}

// -------- main HMMA bf16 kernel: distances + candidate screening --------
extern __shared__ char sm_dyn[];
__global__ __launch_bounds__(256, 1)
void vq_mma_kernel()
{
    __shared__ unsigned s_tile[TILE_M];
    __shared__ float    s_run[TILE_M];

    const int tid  = threadIdx.x;
    const int lane = tid & 31;
    const int warp = tid >> 5;
    const int wm   = warp & 3;      // 4 warps along M
    const int wn   = warp >> 2;     // 2 warps along N
    const int g    = lane >> 2;
    const int q    = lane & 3;
    const int rowbase = blockIdx.x * TILE_M;

    const unsigned smA = smem_u32(sm_dyn);
    const unsigned smB = smA + A_BYTES;
    float* cn_sm = (float*)(sm_dyn + CN_OFF);

    // ---- load resident A tile (128 x 512 bf16), group 0 ----
    {
        const char* src = (const char*)g_zb;
        #pragma unroll
        for (int i = 0; i < 32; i++){
            int f = tid + i * 256;
            int r = f >> 6, qq = f & 63;
            cp16(smA + (unsigned)(r * A_ROW_BYTES + qq * 16),
                 src + (((size_t)(rowbase + r)) << 10) + qq * 16);
        }
        asm volatile("cp.async.commit_group;" ::: "memory");
    }
    // ---- B prologue: chunks 0..2 ----
    #pragma unroll
    for (int c = 0; c < 3; c++){
        load_B(smB, c, tid);
        asm volatile("cp.async.commit_group;" ::: "memory");
    }
    // cnorm -> smem
    for (int i = tid; i < K_CODES; i += 256) cn_sm[i] = g_cnorm[i];
    if (tid < TILE_M){ s_tile[tid] = 0xFFFFFFFFu; s_run[tid] = 3.4e38f; }

    float c[2][8][4];
    #pragma unroll
    for (int am = 0; am < 2; am++)
        #pragma unroll
        for (int an = 0; an < 8; an++)
            #pragma unroll
            for (int r = 0; r < 4; r++) c[am][an][r] = 0.0f;

    const unsigned* Aw = (const unsigned*)sm_dyn;

    for (int ch = 0; ch < TOTAL_CHUNKS; ch++){
        asm volatile("cp.async.wait_group 2;" ::: "memory");
        __syncthreads();

        if (ch + 3 < TOTAL_CHUNKS) load_B(smB, ch + 3, tid);
        asm volatile("cp.async.commit_group;" ::: "memory");

        const unsigned* Bw = (const unsigned*)(sm_dyn + A_BYTES + (ch & 3) * B_STAGE_BYTES);
        const int kw = (ch & 15) * 16;   // word base within A row

        #pragma unroll
        for (int s = 0; s < 2; s++){
            const int wk = kw + s * 8 + q;
            unsigned a[2][4];
            #pragma unroll
            for (int am = 0; am < 2; am++){
                int r0 = wm * 32 + am * 16 + g;
                a[am][0] = Aw[r0 * A_ROW_WORDS + wk];
                a[am][1] = Aw[(r0 + 8) * A_ROW_WORDS + wk];
                a[am][2] = Aw[r0 * A_ROW_WORDS + wk + 4];
                a[am][3] = Aw[(r0 + 8) * A_ROW_WORDS + wk + 4];
            }
            #pragma unroll
            for (int an = 0; an < 8; an++){
                int nr = wn * 64 + an * 8 + g;
                unsigned b0 = Bw[nr * B_ROW_WORDS + s * 8 + q];
                unsigned b1 = Bw[nr * B_ROW_WORDS + s * 8 + q + 4];
                mma_bf16(c[0][an][0], c[0][an][1], c[0][an][2], c[0][an][3],
                         a[0][0], a[0][1], a[0][2], a[0][3], b0, b1);
                mma_bf16(c[1][an][0], c[1][an][1], c[1][an][2], c[1][an][3],
                         a[1][0], a[1][1], a[1][2], a[1][3], b0, b1);
            }
        }

        if ((ch & 15) == 15){
            // ---- epilogue for tile nt ----
            const int nt = ch >> 4;
            float rm[2][2] = {{3.4e38f, 3.4e38f}, {3.4e38f, 3.4e38f}};
            #pragma unroll
            for (int am = 0; am < 2; am++)
                #pragma unroll
                for (int an = 0; an < 8; an++)
                    #pragma unroll
                    for (int r = 0; r < 4; r++){
                        int colg = nt * TILE_N + wn * 64 + an * 8 + q * 2 + (r & 1);
                        float v = fmaf(-2.0f, c[am][an][r], cn_sm[colg]);
                        c[am][an][r] = v;
                        rm[am][r >> 1] = fminf(rm[am][r >> 1], v);
                    }
            #pragma unroll
            for (int am = 0; am < 2; am++)
                #pragma unroll
                for (int h = 0; h < 2; h++){
                    float m = rm[am][h];
                    m = fminf(m, __shfl_xor_sync(0xffffffffu, m, 1));
                    m = fminf(m, __shfl_xor_sync(0xffffffffu, m, 2));
                    if (q == 0)
                        atomicMin(&s_tile[wm * 32 + am * 16 + h * 8 + g], enc_f(m));
                }
            __syncthreads();
            if (tid < TILE_M){
                float m  = dec_f(s_tile[tid]);
                float nr = fminf(s_run[tid], m);
                s_run[tid] = nr;
                s_tile[tid] = 0xFFFFFFFFu;
            }
            __syncthreads();
            float thr[2][2];
            #pragma unroll
            for (int am = 0; am < 2; am++)
                #pragma unroll
                for (int h = 0; h < 2; h++)
                    thr[am][h] = s_run[wm * 32 + am * 16 + h * 8 + g] + MARGIN;
            #pragma unroll
            for (int am = 0; am < 2; am++)
                #pragma unroll
                for (int an = 0; an < 8; an++)
                    #pragma unroll
                    for (int r = 0; r < 4; r++){
                        if (c[am][an][r] < thr[am][r >> 1]){
                            int rowg = rowbase + wm * 32 + am * 16 + (r >> 1) * 8 + g;
                            int colg = nt * TILE_N + wn * 64 + an * 8 + q * 2 + (r & 1);
                            unsigned slot = atomicAdd(&g_cnt[rowg], 1u);
                            if (slot < MAX_CAND) g_cand[rowg * MAX_CAND + slot] = colg;
                        }
                        c[am][an][r] = 0.0f;
                    }
        }
    }
}

// -------- exact fp32 rescue over candidates --------
__global__ void rescue_kernel(const float* __restrict__ z, const float* __restrict__ cb)
{
    const int row = blockIdx.x;
    const int lane = threadIdx.x;
    const unsigned cnt = g_cnt[row];
    const float zn = g_znorm[row];
    const float* zr = z + (size_t)row * D_DIM;

    float best = 3.4e38f;
    int bi = 0x7fffffff;

    if (cnt <= MAX_CAND){
        if (lane < (int)cnt){
            int cix = g_cand[row * MAX_CAND + lane];
            const float* cr = cb + (size_t)cix * D_DIM;
            float acc = 0.0f;
            #pragma unroll 8
            for (int k = 0; k < D_DIM; k++) acc = fmaf(zr[k], cr[k], acc);
            best = fmaf(-2.0f, acc, __fadd_rn(zn, g_cnorm[cix]));
            bi = cix;
        }
    } else {
        for (int cix = lane; cix < K_CODES; cix += 32){
            const float* cr = cb + (size_t)cix * D_DIM;
            float acc = 0.0f;
            #pragma unroll 8
            for (int k = 0; k < D_DIM; k++) acc = fmaf(zr[k], cr[k], acc);
            float d = fmaf(-2.0f, acc, __fadd_rn(zn, g_cnorm[cix]));
            if (d < best){ best = d; bi = cix; }
        }
    }
    #pragma unroll
    for (int o = 16; o > 0; o >>= 1){
        float ob = __shfl_down_sync(0xffffffffu, best, o);
        int   oi = __shfl_down_sync(0xffffffffu, bi, o);
        if (ob < best || (ob == best && oi < bi)){ best = ob; bi = oi; }
    }
    if (lane == 0){ g_idx[row] = bi; g_partial[row] = best; }
}

// -------- gather z_q + indices --------
__global__ void gather_kernel(const float* __restrict__ cb, float* __restrict__ out)
{
    int row = blockIdx.x, t = threadIdx.x;
    int id = g_idx[row];
    float4 v = ((const float4*)(cb + (size_t)id * D_DIM))[t];
    ((float4*)(out + (size_t)row * D_DIM))[t] = v;
    if (t == 0) out[(size_t)N_ROWS * D_DIM + row] = (float)id;
}

// -------- final loss --------
__global__ void loss_kernel(float* __restrict__ out){
    __shared__ double red[256];
    int t = threadIdx.x;
    double a = 0.0;
    for (int j = t; j < N_ROWS; j += 256) a += (double)g_partial[j];
    red[t] = a; __syncthreads();
    #pragma unroll
    for (int s = 128; s > 0; s >>= 1){
        if (t < s) red[t] += red[t + s];
        __syncthreads();
    }
    if (t == 0){
        float v = (float)(red[0] / ((double)N_ROWS * (double)D_DIM));
        out[(size_t)N_ROWS * D_DIM + N_ROWS] = __fadd_rn(v, 0.25f * v);
    }
}

extern "C" void kernel_launch(void* const* d_in, const int* in_sizes, int n_in,
                              void* d_out, int out_size)
{
    const float* z  = (const float*)d_in[0];   // [16384, 512]
    const float* cb = (const float*)d_in[1];   // [4096, 512]
    float* out = (float*)d_out;                // [z_q (N*D)] [idx (N)] [loss (1)]

    cudaFuncSetAttribute(vq_mma_kernel,
                         cudaFuncAttributeMaxDynamicSharedMemorySize, DYN_BYTES);

    init_cnt_kernel<<<(N_ROWS + 1023) / 1024, 1024>>>();
    convz_kernel<<<(N_ROWS * D_DIM / 4 + 255) / 256, 256>>>(z);
    convc_kernel<<<(K_CODES * D_DIM / 4 + 255) / 256, 256>>>(cb);
    znorm_kernel<<<N_ROWS / 8, 256>>>(z);
    cnorm_kernel<<<K_CODES / 8, 256>>>(cb);
    vq_mma_kernel<<<N_ROWS / TILE_M, 256, DYN_BYTES>>>();
    rescue_kernel<<<N_ROWS, 32>>>(z, cb);
    gather_kernel<<<N_ROWS, 128>>>(cb, out);
    loss_kernel<<<1, 256>>>(out);
}